// round 8
// baseline (speedup 1.0000x reference)
#include <cuda_runtime.h>
#include <cuda_bf16.h>
#include <cstdint>

#define H   2048
#define ISZ 4096
#define NE  8
#define T   2048

// ---------------- scratch -----------------------------------------------------
__device__ float g_act[4096UL * 4096UL];   // rows 0..2047 shared act, 2048..4095 routed (compacted)
__device__ float g_scale[T];
__device__ float g_scale_perm[T];
__device__ int   g_eid[T];
__device__ int   g_perm[T];
__device__ int   g_off[NE + 1];

#define MMA_BF16(d, a, b)                                                      \
    asm volatile("mma.sync.aligned.m16n8k16.row.col.f32.bf16.bf16.f32 "        \
                 "{%0,%1,%2,%3},{%4,%5,%6,%7},{%8,%9},{%0,%1,%2,%3};"          \
                 : "+f"(d[0]), "+f"(d[1]), "+f"(d[2]), "+f"(d[3])              \
                 : "r"(a[0]), "r"(a[1]), "r"(a[2]), "r"(a[3]),                 \
                   "r"(b[0]), "r"(b[1]))

__device__ __forceinline__ void ldsm_x4(uint32_t* r, uint32_t addr) {
    asm volatile("ldmatrix.sync.aligned.m8n8.x4.shared.b16 {%0,%1,%2,%3}, [%4];"
                 : "=r"(r[0]), "=r"(r[1]), "=r"(r[2]), "=r"(r[3]) : "r"(addr));
}
__device__ __forceinline__ void ldsm_x4t(uint32_t* r, uint32_t addr) {
    asm volatile("ldmatrix.sync.aligned.m8n8.x4.trans.shared.b16 {%0,%1,%2,%3}, [%4];"
                 : "=r"(r[0]), "=r"(r[1]), "=r"(r[2]), "=r"(r[3]) : "r"(addr));
}

// split pair (f0,f1) -> packed bf16x2 hi word + lo (residual) word.
__device__ __forceinline__ void bpair(float f0, float f1, uint32_t& hw, uint32_t& lw) {
    __nv_bfloat162 h = __floats2bfloat162_rn(f0, f1);
    uint32_t hu = *reinterpret_cast<uint32_t*>(&h);
    float r0 = f0 - __uint_as_float(hu << 16);
    float r1 = f1 - __uint_as_float(hu & 0xffff0000u);
    __nv_bfloat162 l = __floats2bfloat162_rn(r0, r1);
    hw = hu;
    lw = *reinterpret_cast<uint32_t*>(&l);
}
__device__ __forceinline__ void pack8(const float4& v0, const float4& v1, uint4& hi, uint4& lo) {
    uint32_t h0, h1, h2, h3, l0, l1, l2, l3;
    bpair(v0.x, v0.y, h0, l0); bpair(v0.z, v0.w, h1, l1);
    bpair(v1.x, v1.y, h2, l2); bpair(v1.z, v1.w, h3, l3);
    hi = make_uint4(h0, h1, h2, h3); lo = make_uint4(l0, l1, l2, l3);
}

// ---------------- router ------------------------------------------------------
__global__ void router_kernel(const float* __restrict__ x, const float* __restrict__ rw) {
    const int t = blockIdx.x;
    const int tid = threadIdx.x;
    float acc[NE];
#pragma unroll
    for (int e = 0; e < NE; e++) acc[e] = 0.f;
    const float* xr = x + (size_t)t * H;
    for (int h = tid; h < H; h += 256) {
        float xv = xr[h];
#pragma unroll
        for (int e = 0; e < NE; e++) acc[e] += xv * rw[e * H + h];
    }
#pragma unroll
    for (int e = 0; e < NE; e++)
#pragma unroll
        for (int o = 16; o > 0; o >>= 1) acc[e] += __shfl_xor_sync(0xffffffffu, acc[e], o);
    __shared__ float red[NE][8];
    if ((tid & 31) == 0) {
#pragma unroll
        for (int e = 0; e < NE; e++) red[e][tid >> 5] = acc[e];
    }
    __syncthreads();
    if (tid == 0) {
        float best = -1e30f; int be = 0;
#pragma unroll
        for (int e = 0; e < NE; e++) {
            float v = 0.f;
#pragma unroll
            for (int w = 0; w < 8; w++) v += red[e][w];
            if (v > best) { best = v; be = e; }
        }
        g_scale[t] = 1.f / (1.f + expf(-best));
        g_eid[t] = be;
    }
}

// ---------------- bucket ------------------------------------------------------
__global__ void bucket_kernel() {
    __shared__ int cnt[NE], cur[NE];
    const int tid = threadIdx.x;
    if (tid < NE) cnt[tid] = 0;
    __syncthreads();
    for (int t = tid; t < T; t += 256) atomicAdd(&cnt[g_eid[t]], 1);
    __syncthreads();
    if (tid == 0) {
        int a = 0;
        for (int e = 0; e < NE; e++) { g_off[e] = a; cur[e] = a; a += cnt[e]; }
        g_off[NE] = a;
    }
    __syncthreads();
    for (int t = tid; t < T; t += 256) {
        int e = g_eid[t];
        int p = atomicAdd(&cur[e], 1);
        g_perm[p] = t;
        g_scale_perm[p] = g_scale[t];
    }
}

// SMEM (dynamic, bytes):
// A: 2buf x 2planes x 128rows x 12words x 4B = 24576
// B: 2buf x 2planes x 16k x 264bf16 x 2B    = 33792
#define PA    6144
#define ABUF  12288
#define BOFF  24576
#define PB    8448
#define BBUF  16896
#define SMEM_SZ 58368

// ---------------- GEMM1: x[M,2048] x (gate|up)[2048, 128+128 cols] + SwiGLU ---
// CTA 128m x (128 gate + 128 up). Warp: 32m x (64g + 64u). BK=16, double buffer.
__global__ __launch_bounds__(256) void gemm1_kernel(
    const float* __restrict__ x, const float* __restrict__ gup,
    const float* __restrict__ sg, const float* __restrict__ su)
{
    extern __shared__ __align__(16) char smem[];
    const uint32_t sb = (uint32_t)__cvta_generic_to_shared(smem);

    const int mTile = blockIdx.x, nTile = blockIdx.y, e = blockIdx.z;
    int M, offE, actBase;
    size_t ldb;
    const float *pg, *pu;
    if (e < NE) {
        offE = g_off[e]; M = g_off[e + 1] - offE;
        if (mTile * 128 >= M) return;
        pg = gup + (size_t)e * H * (2 * ISZ) + nTile * 128;
        pu = pg + ISZ; ldb = 2 * ISZ; actBase = T + offE;
    } else {
        offE = 0; M = T;
        pg = sg + nTile * 128; pu = su + nTile * 128; ldb = ISZ; actBase = 0;
    }
    const int tid = threadIdx.x, lane = tid & 31, warp = tid >> 5;
    const int wm = warp & 3, wn = warp >> 2;

    // A loader: row = tid>>1, 8 floats at (tid&1)*8
    const int arow = tid >> 1, akc = (tid & 1) * 8;
    const uint32_t aw = (uint32_t)(arow * 48 + (tid & 1) * 16);
    const int lr = mTile * 128 + arow;
    const float* aptr;
    if (e < NE) aptr = x + (size_t)g_perm[offE + min(lr, M - 1)] * H + akc;
    else        aptr = x + (size_t)lr * H + akc;

    // B loader: krow = tid>>4 (16 rows), 16 floats at (tid&15)*16.
    // n0 < 128 -> gate col n0 ; else up col n0-128.
    const int bkrow = tid >> 4, bn0 = (tid & 15) * 16;
    const float* bptr = ((bn0 < 128) ? (pg + bn0) : (pu + (bn0 - 128))) + (size_t)bkrow * ldb;
    const uint32_t bw = (uint32_t)(bkrow * 528 + bn0 * 2);

    // fragment offsets
    const int tq = lane >> 3, tr = lane & 7;
    uint32_t offA[2];
#pragma unroll
    for (int mi = 0; mi < 2; mi++) {
        int row = wm * 32 + mi * 16 + (tq & 1) * 8 + tr;
        offA[mi] = (uint32_t)(row * 48 + (tq >> 1) * 16);
    }
    const int kB = (tq & 1) * 8 + tr, ngB = tq >> 1;
    uint32_t offB[2][4];
#pragma unroll
    for (int hh = 0; hh < 2; hh++)
#pragma unroll
        for (int g = 0; g < 4; g++)
            offB[hh][g] = (uint32_t)(kB * 528 + ((hh * 128 + wn * 64 + g * 16) + ngB * 8) * 2);

    float acc[2][2][8][4];
#pragma unroll
    for (int h = 0; h < 2; h++)
#pragma unroll
        for (int mi = 0; mi < 2; mi++)
#pragma unroll
            for (int ni = 0; ni < 8; ni++)
#pragma unroll
                for (int r = 0; r < 4; r++) acc[h][mi][ni][r] = 0.f;

    // prologue: fill buffer 0
    {
        float4 a0 = *(const float4*)aptr;
        float4 a1 = *(const float4*)(aptr + 4);
        float4 b0 = *(const float4*)bptr;
        float4 b1 = *(const float4*)(bptr + 4);
        float4 b2 = *(const float4*)(bptr + 8);
        float4 b3 = *(const float4*)(bptr + 12);
        uint4 hi, lo;
        pack8(a0, a1, hi, lo);
        *(uint4*)(smem + aw) = hi;
        *(uint4*)(smem + PA + aw) = lo;
        uint4 h01, l01, h23, l23;
        pack8(b0, b1, h01, l01);
        pack8(b2, b3, h23, l23);
        *(uint4*)(smem + BOFF + bw) = h01;
        *(uint4*)(smem + BOFF + bw + 16) = h23;
        *(uint4*)(smem + BOFF + PB + bw) = l01;
        *(uint4*)(smem + BOFF + PB + bw + 16) = l23;
    }
    __syncthreads();

    const int KT = H / 16;
    for (int kt = 0; kt < KT; ++kt) {
        const int s = kt & 1;
        float4 a0, a1, b0, b1, b2, b3;
        if (kt + 1 < KT) {
            const float* ap = aptr + (kt + 1) * 16;
            a0 = *(const float4*)ap;
            a1 = *(const float4*)(ap + 4);
            const float* bp = bptr + (size_t)(kt + 1) * 16 * ldb;
            b0 = *(const float4*)bp;
            b1 = *(const float4*)(bp + 4);
            b2 = *(const float4*)(bp + 8);
            b3 = *(const float4*)(bp + 12);
        }

        const uint32_t aS = sb + s * ABUF;
        const uint32_t bS = sb + BOFF + s * BBUF;
        uint32_t ah[2][4], al[2][4];
        ldsm_x4(ah[0], aS + offA[0]);
        ldsm_x4(ah[1], aS + offA[1]);
        ldsm_x4(al[0], aS + PA + offA[0]);
        ldsm_x4(al[1], aS + PA + offA[1]);
#pragma unroll
        for (int hh = 0; hh < 2; ++hh) {
#pragma unroll
            for (int g = 0; g < 4; ++g) {
                uint32_t bh4[4], bl4[4];
                ldsm_x4t(bh4, bS + offB[hh][g]);
                ldsm_x4t(bl4, bS + PB + offB[hh][g]);
#pragma unroll
                for (int sub = 0; sub < 2; ++sub) {
                    const int ni = 2 * g + sub;
                    uint32_t bh[2] = { bh4[sub * 2], bh4[sub * 2 + 1] };
                    uint32_t bl[2] = { bl4[sub * 2], bl4[sub * 2 + 1] };
#pragma unroll
                    for (int mi = 0; mi < 2; ++mi) {
                        MMA_BF16(acc[hh][mi][ni], al[mi], bh);
                        MMA_BF16(acc[hh][mi][ni], ah[mi], bl);
                        MMA_BF16(acc[hh][mi][ni], ah[mi], bh);
                    }
                }
            }
        }

        if (kt + 1 < KT) {
            const int s2 = s ^ 1;
            char* dst = smem + s2 * ABUF;
            uint4 hi, lo;
            pack8(a0, a1, hi, lo);
            *(uint4*)(dst + aw) = hi;
            *(uint4*)(dst + PA + aw) = lo;
            char* bdst = smem + BOFF + s2 * BBUF;
            uint4 h01, l01, h23, l23;
            pack8(b0, b1, h01, l01);
            pack8(b2, b3, h23, l23);
            *(uint4*)(bdst + bw) = h01;
            *(uint4*)(bdst + bw + 16) = h23;
            *(uint4*)(bdst + PB + bw) = l01;
            *(uint4*)(bdst + PB + bw + 16) = l23;
        }
        __syncthreads();
    }

    // epilogue: act = (s*up) * silu(s*gate)
#pragma unroll
    for (int mi = 0; mi < 2; ++mi) {
        const int r0 = mTile * 128 + wm * 32 + mi * 16 + (lane >> 2);
        const int r1 = r0 + 8;
        const bool v0 = r0 < M, v1 = r1 < M;
        float s0 = 1.f, s1 = 1.f;
        if (e < NE) {
            s0 = v0 ? g_scale_perm[offE + r0] : 0.f;
            s1 = v1 ? g_scale_perm[offE + r1] : 0.f;
        }
#pragma unroll
        for (int ni = 0; ni < 8; ++ni) {
            const int col = nTile * 128 + wn * 64 + ni * 8 + (lane & 3) * 2;
            if (v0) {
                float gA = s0 * acc[0][mi][ni][0], gB = s0 * acc[0][mi][ni][1];
                float uA = s0 * acc[1][mi][ni][0], uB = s0 * acc[1][mi][ni][1];
                float a0 = uA * (gA / (1.f + expf(-gA)));
                float a1 = uB * (gB / (1.f + expf(-gB)));
                *(float2*)&g_act[(size_t)(actBase + r0) * ISZ + col] = make_float2(a0, a1);
            }
            if (v1) {
                float gA = s1 * acc[0][mi][ni][2], gB = s1 * acc[0][mi][ni][3];
                float uA = s1 * acc[1][mi][ni][2], uB = s1 * acc[1][mi][ni][3];
                float a0 = uA * (gA / (1.f + expf(-gA)));
                float a1 = uB * (gB / (1.f + expf(-gB)));
                *(float2*)&g_act[(size_t)(actBase + r1) * ISZ + col] = make_float2(a0, a1);
            }
        }
    }
}

// ---------------- GEMM2: act[M,4096] x down[4096,2048] ------------------------
// CTA 128m x 256n. Warp: 32m x 128n (mi=2, ni=16). BK=16, double buffer.
__global__ __launch_bounds__(256) void gemm2_kernel(
    const float* __restrict__ dwn, const float* __restrict__ sdwn,
    float* __restrict__ out, int routed)
{
    extern __shared__ __align__(16) char smem[];
    const uint32_t sb = (uint32_t)__cvta_generic_to_shared(smem);

    const int mTile = blockIdx.x, nTile = blockIdx.y;
    int M, offE, actBase;
    const float* Bd;
    if (routed) {
        const int e = blockIdx.z;
        offE = g_off[e]; M = g_off[e + 1] - offE;
        if (mTile * 128 >= M) return;
        actBase = T + offE;
        Bd = dwn + (size_t)e * ISZ * H + nTile * 256;
    } else {
        offE = 0; M = T; actBase = 0;
        Bd = sdwn + nTile * 256;
    }
    const int tid = threadIdx.x, lane = tid & 31, warp = tid >> 5;
    const int wm = warp & 3, wn = warp >> 2;

    const int arow = tid >> 1, akc = (tid & 1) * 8;
    const uint32_t aw = (uint32_t)(arow * 48 + (tid & 1) * 16);
    const int lr = mTile * 128 + arow;
    const float* aptr = g_act + (size_t)(actBase + min(lr, M - 1)) * ISZ + akc;

    const int bkrow = tid >> 4, bn0 = (tid & 15) * 16;
    const float* bptr = Bd + (size_t)bkrow * H + bn0;
    const uint32_t bw = (uint32_t)(bkrow * 528 + bn0 * 2);

    const int tq = lane >> 3, tr = lane & 7;
    uint32_t offA[2];
#pragma unroll
    for (int mi = 0; mi < 2; mi++) {
        int row = wm * 32 + mi * 16 + (tq & 1) * 8 + tr;
        offA[mi] = (uint32_t)(row * 48 + (tq >> 1) * 16);
    }
    const int kB = (tq & 1) * 8 + tr, ngB = tq >> 1;
    uint32_t offB[8];
#pragma unroll
    for (int g = 0; g < 8; g++)
        offB[g] = (uint32_t)(kB * 528 + ((wn * 128 + g * 16) + ngB * 8) * 2);

    float acc[2][16][4];
#pragma unroll
    for (int mi = 0; mi < 2; mi++)
#pragma unroll
        for (int ni = 0; ni < 16; ni++)
#pragma unroll
            for (int r = 0; r < 4; r++) acc[mi][ni][r] = 0.f;

    {
        float4 a0 = *(const float4*)aptr;
        float4 a1 = *(const float4*)(aptr + 4);
        float4 b0 = *(const float4*)bptr;
        float4 b1 = *(const float4*)(bptr + 4);
        float4 b2 = *(const float4*)(bptr + 8);
        float4 b3 = *(const float4*)(bptr + 12);
        uint4 hi, lo;
        pack8(a0, a1, hi, lo);
        *(uint4*)(smem + aw) = hi;
        *(uint4*)(smem + PA + aw) = lo;
        uint4 h01, l01, h23, l23;
        pack8(b0, b1, h01, l01);
        pack8(b2, b3, h23, l23);
        *(uint4*)(smem + BOFF + bw) = h01;
        *(uint4*)(smem + BOFF + bw + 16) = h23;
        *(uint4*)(smem + BOFF + PB + bw) = l01;
        *(uint4*)(smem + BOFF + PB + bw + 16) = l23;
    }
    __syncthreads();

    const int KT = ISZ / 16;
    for (int kt = 0; kt < KT; ++kt) {
        const int s = kt & 1;
        float4 a0, a1, b0, b1, b2, b3;
        if (kt + 1 < KT) {
            const float* ap = aptr + (kt + 1) * 16;
            a0 = *(const float4*)ap;
            a1 = *(const float4*)(ap + 4);
            const float* bp = bptr + (size_t)(kt + 1) * 16 * H;
            b0 = *(const float4*)bp;
            b1 = *(const float4*)(bp + 4);
            b2 = *(const float4*)(bp + 8);
            b3 = *(const float4*)(bp + 12);
        }

        const uint32_t aS = sb + s * ABUF;
        const uint32_t bS = sb + BOFF + s * BBUF;
        uint32_t ah[2][4], al[2][4];
        ldsm_x4(ah[0], aS + offA[0]);
        ldsm_x4(ah[1], aS + offA[1]);
        ldsm_x4(al[0], aS + PA + offA[0]);
        ldsm_x4(al[1], aS + PA + offA[1]);
#pragma unroll
        for (int g = 0; g < 8; ++g) {
            uint32_t bh4[4], bl4[4];
            ldsm_x4t(bh4, bS + offB[g]);
            ldsm_x4t(bl4, bS + PB + offB[g]);
#pragma unroll
            for (int sub = 0; sub < 2; ++sub) {
                const int ni = 2 * g + sub;
                uint32_t bh[2] = { bh4[sub * 2], bh4[sub * 2 + 1] };
                uint32_t bl[2] = { bl4[sub * 2], bl4[sub * 2 + 1] };
#pragma unroll
                for (int mi = 0; mi < 2; ++mi) {
                    MMA_BF16(acc[mi][ni], al[mi], bh);
                    MMA_BF16(acc[mi][ni], ah[mi], bl);
                    MMA_BF16(acc[mi][ni], ah[mi], bh);
                }
            }
        }

        if (kt + 1 < KT) {
            const int s2 = s ^ 1;
            char* dst = smem + s2 * ABUF;
            uint4 hi, lo;
            pack8(a0, a1, hi, lo);
            *(uint4*)(dst + aw) = hi;
            *(uint4*)(dst + PA + aw) = lo;
            char* bdst = smem + BOFF + s2 * BBUF;
            uint4 h01, l01, h23, l23;
            pack8(b0, b1, h01, l01);
            pack8(b2, b3, h23, l23);
            *(uint4*)(bdst + bw) = h01;
            *(uint4*)(bdst + bw + 16) = h23;
            *(uint4*)(bdst + PB + bw) = l01;
            *(uint4*)(bdst + PB + bw + 16) = l23;
        }
        __syncthreads();
    }

#pragma unroll
    for (int mi = 0; mi < 2; ++mi) {
        const int r0 = mTile * 128 + wm * 32 + mi * 16 + (lane >> 2);
        const int r1 = r0 + 8;
        const bool v0 = r0 < M, v1 = r1 < M;
        int t0 = 0, t1 = 0;
        if (routed) {
            if (v0) t0 = g_perm[offE + r0];
            if (v1) t1 = g_perm[offE + r1];
        } else { t0 = r0; t1 = r1; }
#pragma unroll
        for (int ni = 0; ni < 16; ++ni) {
            const int col = nTile * 256 + wn * 128 + ni * 8 + (lane & 3) * 2;
            if (v0) {
                float2* p = (float2*)&out[(size_t)t0 * H + col];
                if (routed) {
                    float2 v = *p;
                    v.x += acc[mi][ni][0]; v.y += acc[mi][ni][1];
                    *p = v;
                } else {
                    *p = make_float2(acc[mi][ni][0], acc[mi][ni][1]);
                }
            }
            if (v1) {
                float2* p = (float2*)&out[(size_t)t1 * H + col];
                if (routed) {
                    float2 v = *p;
                    v.x += acc[mi][ni][2]; v.y += acc[mi][ni][3];
                    *p = v;
                } else {
                    *p = make_float2(acc[mi][ni][2], acc[mi][ni][3]);
                }
            }
        }
    }
}

// ---------------- launch ------------------------------------------------------
extern "C" void kernel_launch(void* const* d_in, const int* in_sizes, int n_in,
                              void* d_out, int out_size) {
    const float* x   = (const float*)d_in[0];
    const float* rw  = (const float*)d_in[1];
    const float* gup = (const float*)d_in[2];
    const float* dwn = (const float*)d_in[3];
    const float* sg  = (const float*)d_in[4];
    const float* su  = (const float*)d_in[5];
    const float* sd  = (const float*)d_in[6];
    float* out = (float*)d_out;

    cudaFuncSetAttribute(gemm1_kernel, cudaFuncAttributeMaxDynamicSharedMemorySize, SMEM_SZ);
    cudaFuncSetAttribute(gemm2_kernel, cudaFuncAttributeMaxDynamicSharedMemorySize, SMEM_SZ);

    router_kernel<<<T, 256>>>(x, rw);
    bucket_kernel<<<1, 256>>>();
    gemm1_kernel<<<dim3(16, ISZ / 128, NE + 1), 256, SMEM_SZ>>>(x, gup, sg, su);
    gemm2_kernel<<<dim3(16, H / 256, 1), 256, SMEM_SZ>>>(dwn, sd, out, 0);   // shared: writes out
    gemm2_kernel<<<dim3(16, H / 256, NE), 256, SMEM_SZ>>>(dwn, sd, out, 1);  // routed: adds
}

// round 11
// speedup vs baseline: 1.2227x; 1.2227x over previous
#include <cuda_runtime.h>
#include <cuda_fp16.h>
#include <cstdint>

#define H   2048
#define ISZ 4096
#define NE  8
#define T   2048

// ---------------- scratch -----------------------------------------------------
__device__ float g_act[4096UL * 4096UL];   // rows 0..2047 shared act, 2048..4095 routed (compacted)
__device__ float g_scale[T];
__device__ float g_scale_perm[T];
__device__ int   g_eid[T];
__device__ int   g_perm[T];
__device__ int   g_off[NE + 1];

#define MMA_F16(d, a, b)                                                       \
    asm volatile("mma.sync.aligned.m16n8k16.row.col.f32.f16.f16.f32 "          \
                 "{%0,%1,%2,%3},{%4,%5,%6,%7},{%8,%9},{%0,%1,%2,%3};"          \
                 : "+f"(d[0]), "+f"(d[1]), "+f"(d[2]), "+f"(d[3])              \
                 : "r"(a[0]), "r"(a[1]), "r"(a[2]), "r"(a[3]),                 \
                   "r"(b[0]), "r"(b[1]))

__device__ __forceinline__ void ldsm_x4(uint32_t* r, uint32_t addr) {
    asm volatile("ldmatrix.sync.aligned.m8n8.x4.shared.b16 {%0,%1,%2,%3}, [%4];"
                 : "=r"(r[0]), "=r"(r[1]), "=r"(r[2]), "=r"(r[3]) : "r"(addr));
}
__device__ __forceinline__ void ldsm_x4t(uint32_t* r, uint32_t addr) {
    asm volatile("ldmatrix.sync.aligned.m8n8.x4.trans.shared.b16 {%0,%1,%2,%3}, [%4];"
                 : "=r"(r[0]), "=r"(r[1]), "=r"(r[2]), "=r"(r[3]) : "r"(addr));
}

// pack 8 fp32 -> 8 fp16 (one uint4)
__device__ __forceinline__ uint4 hpack8(const float4& v0, const float4& v1) {
    __half2 h0 = __floats2half2_rn(v0.x, v0.y);
    __half2 h1 = __floats2half2_rn(v0.z, v0.w);
    __half2 h2 = __floats2half2_rn(v1.x, v1.y);
    __half2 h3 = __floats2half2_rn(v1.z, v1.w);
    return make_uint4(*(uint32_t*)&h0, *(uint32_t*)&h1, *(uint32_t*)&h2, *(uint32_t*)&h3);
}

// ---------------- router ------------------------------------------------------
__global__ void router_kernel(const float* __restrict__ x, const float* __restrict__ rw) {
    const int t = blockIdx.x;
    const int tid = threadIdx.x;
    float acc[NE];
#pragma unroll
    for (int e = 0; e < NE; e++) acc[e] = 0.f;
    const float* xr = x + (size_t)t * H;
    for (int h = tid; h < H; h += 256) {
        float xv = xr[h];
#pragma unroll
        for (int e = 0; e < NE; e++) acc[e] += xv * rw[e * H + h];
    }
#pragma unroll
    for (int e = 0; e < NE; e++)
#pragma unroll
        for (int o = 16; o > 0; o >>= 1) acc[e] += __shfl_xor_sync(0xffffffffu, acc[e], o);
    __shared__ float red[NE][8];
    if ((tid & 31) == 0) {
#pragma unroll
        for (int e = 0; e < NE; e++) red[e][tid >> 5] = acc[e];
    }
    __syncthreads();
    if (tid == 0) {
        float best = -1e30f; int be = 0;
#pragma unroll
        for (int e = 0; e < NE; e++) {
            float v = 0.f;
#pragma unroll
            for (int w = 0; w < 8; w++) v += red[e][w];
            if (v > best) { best = v; be = e; }
        }
        g_scale[t] = 1.f / (1.f + expf(-best));
        g_eid[t] = be;
    }
}

// ---------------- bucket ------------------------------------------------------
__global__ void bucket_kernel() {
    __shared__ int cnt[NE], cur[NE];
    const int tid = threadIdx.x;
    if (tid < NE) cnt[tid] = 0;
    __syncthreads();
    for (int t = tid; t < T; t += 256) atomicAdd(&cnt[g_eid[t]], 1);
    __syncthreads();
    if (tid == 0) {
        int a = 0;
        for (int e = 0; e < NE; e++) { g_off[e] = a; cur[e] = a; a += cnt[e]; }
        g_off[NE] = a;
    }
    __syncthreads();
    for (int t = tid; t < T; t += 256) {
        int e = g_eid[t];
        int p = atomicAdd(&cur[e], 1);
        g_perm[p] = t;
        g_scale_perm[p] = g_scale[t];
    }
}

// ---------------- GEMM1: x[M,2048] x (gate|up)[2048, 64+64] + SwiGLU ----------
// CTA 128m x (64g + 64u), warp 32m x (32g + 32u). BK=16, double buffer, fp16.
__global__ __launch_bounds__(256) void gemm1_kernel(
    const float* __restrict__ x, const float* __restrict__ gup,
    const float* __restrict__ sg, const float* __restrict__ su)
{
    __shared__ __align__(16) __half As[2][128][24];       // 48B rows (32B data + pad)
    __shared__ __align__(16) __half Bs[2][2][16][72];     // [buf][g/u][k][n] 144B rows
    const int mTile = blockIdx.x, nTile = blockIdx.y, e = blockIdx.z;
    int M, offE, actBase;
    size_t ldb;
    const float *pg, *pu;
    if (e < NE) {
        offE = g_off[e]; M = g_off[e + 1] - offE;
        if (mTile * 128 >= M) return;
        pg = gup + (size_t)e * H * (2 * ISZ) + nTile * 64;
        pu = pg + ISZ; ldb = 2 * ISZ; actBase = T + offE;
    } else {
        offE = 0; M = T;
        pg = sg + nTile * 64; pu = su + nTile * 64; ldb = ISZ; actBase = 0;
    }
    const int tid = threadIdx.x, lane = tid & 31, warp = tid >> 5;
    const int wm = warp & 3, wn = warp >> 2;

    // A loader: row = tid>>1, 8 floats at (tid&1)*8
    const int arow = tid >> 1, akc = (tid & 1) * 8;
    const uint32_t aw = (uint32_t)(arow * 48 + (tid & 1) * 16);
    const int lr = mTile * 128 + arow;
    const float* aptr;
    if (e < NE) aptr = x + (size_t)g_perm[offE + min(lr, M - 1)] * H + akc;
    else        aptr = x + (size_t)lr * H + akc;

    // B loader: half = tid>>7, k row = (tid>>3)&15, n0 = (tid&7)*8
    const int bhalf = tid >> 7, bkr = (tid >> 3) & 15, bn0 = (tid & 7) * 8;
    const float* bptr = (bhalf ? pu : pg) + (size_t)bkr * ldb + bn0;
    const uint32_t bw = (uint32_t)(bhalf * 2304 + bkr * 144 + bn0 * 2);

    const uint32_t baseA = (uint32_t)__cvta_generic_to_shared(&As[0][0][0]);
    const uint32_t baseB = (uint32_t)__cvta_generic_to_shared(&Bs[0][0][0][0]);
    const int SA = 128 * 48, SB = 2 * 16 * 144;

    // fragment offsets
    const int tq = lane >> 3, tr = lane & 7;
    uint32_t offA[2];
#pragma unroll
    for (int mi = 0; mi < 2; mi++) {
        int row = wm * 32 + mi * 16 + (tq & 1) * 8 + tr;
        offA[mi] = (uint32_t)(row * 48 + (tq >> 1) * 16);
    }
    const int kB = (tq & 1) * 8 + tr, ngB = tq >> 1;
    uint32_t offB[2][2];
#pragma unroll
    for (int hh = 0; hh < 2; hh++)
#pragma unroll
        for (int g = 0; g < 2; g++)
            offB[hh][g] = (uint32_t)(hh * 2304 + kB * 144 + (wn * 32 + g * 16 + ngB * 8) * 2);

    float acc[2][2][4][4];
#pragma unroll
    for (int h = 0; h < 2; h++)
#pragma unroll
        for (int mi = 0; mi < 2; mi++)
#pragma unroll
            for (int ni = 0; ni < 4; ni++)
#pragma unroll
                for (int r = 0; r < 4; r++) acc[h][mi][ni][r] = 0.f;

    // prologue
    {
        float4 a0 = *(const float4*)aptr;
        float4 a1 = *(const float4*)(aptr + 4);
        float4 b0 = *(const float4*)bptr;
        float4 b1 = *(const float4*)(bptr + 4);
        *(uint4*)((char*)As + aw) = hpack8(a0, a1);
        *(uint4*)((char*)Bs + bw) = hpack8(b0, b1);
    }
    __syncthreads();

    const int KT = H / 16;
    for (int kt = 0; kt < KT; ++kt) {
        const int s = kt & 1;
        float4 a0, a1, b0, b1;
        if (kt + 1 < KT) {
            const float* ap = aptr + (kt + 1) * 16;
            a0 = *(const float4*)ap;
            a1 = *(const float4*)(ap + 4);
            const float* bp = bptr + (size_t)(kt + 1) * 16 * ldb;
            b0 = *(const float4*)bp;
            b1 = *(const float4*)(bp + 4);
        }

        const uint32_t aS = baseA + s * SA;
        const uint32_t bS = baseB + s * SB;
        uint32_t af[2][4];
        ldsm_x4(af[0], aS + offA[0]);
        ldsm_x4(af[1], aS + offA[1]);
#pragma unroll
        for (int hh = 0; hh < 2; ++hh) {
#pragma unroll
            for (int g = 0; g < 2; ++g) {
                uint32_t b4[4];
                ldsm_x4t(b4, bS + offB[hh][g]);
#pragma unroll
                for (int sub = 0; sub < 2; ++sub) {
                    const int ni = 2 * g + sub;
                    uint32_t bf[2] = { b4[sub * 2], b4[sub * 2 + 1] };
#pragma unroll
                    for (int mi = 0; mi < 2; ++mi)
                        MMA_F16(acc[hh][mi][ni], af[mi], bf);
                }
            }
        }

        if (kt + 1 < KT) {
            const int s2 = s ^ 1;
            *(uint4*)((char*)As + s2 * SA + aw) = hpack8(a0, a1);
            *(uint4*)((char*)Bs + s2 * SB + bw) = hpack8(b0, b1);
        }
        __syncthreads();
    }

    // epilogue: act = (s*up) * silu(s*gate)
#pragma unroll
    for (int mi = 0; mi < 2; ++mi) {
        const int r0 = mTile * 128 + wm * 32 + mi * 16 + (lane >> 2);
        const int r1 = r0 + 8;
        const bool v0 = r0 < M, v1 = r1 < M;
        float s0 = 1.f, s1 = 1.f;
        if (e < NE) {
            s0 = v0 ? g_scale_perm[offE + r0] : 0.f;
            s1 = v1 ? g_scale_perm[offE + r1] : 0.f;
        }
#pragma unroll
        for (int ni = 0; ni < 4; ++ni) {
            const int col = nTile * 64 + wn * 32 + ni * 8 + (lane & 3) * 2;
            if (v0) {
                float gA = s0 * acc[0][mi][ni][0], gB = s0 * acc[0][mi][ni][1];
                float uA = s0 * acc[1][mi][ni][0], uB = s0 * acc[1][mi][ni][1];
                float a0 = uA * (gA / (1.f + expf(-gA)));
                float a1 = uB * (gB / (1.f + expf(-gB)));
                *(float2*)&g_act[(size_t)(actBase + r0) * ISZ + col] = make_float2(a0, a1);
            }
            if (v1) {
                float gA = s1 * acc[0][mi][ni][2], gB = s1 * acc[0][mi][ni][3];
                float uA = s1 * acc[1][mi][ni][2], uB = s1 * acc[1][mi][ni][3];
                float a0 = uA * (gA / (1.f + expf(-gA)));
                float a1 = uB * (gB / (1.f + expf(-gB)));
                *(float2*)&g_act[(size_t)(actBase + r1) * ISZ + col] = make_float2(a0, a1);
            }
        }
    }
}

// ---------------- GEMM2: act[M,4096] x down[4096,2048] ------------------------
// CTA 128m x 128n, warp 32m x 64n. BK=16, double buffer, fp16.
__global__ __launch_bounds__(256) void gemm2_kernel(
    const float* __restrict__ dwn, const float* __restrict__ sdwn,
    float* __restrict__ out, int routed)
{
    __shared__ __align__(16) __half As[2][128][24];
    __shared__ __align__(16) __half Bs[2][16][136];       // 272B rows
    const int mTile = blockIdx.x, nTile = blockIdx.y;
    int M, offE, actBase;
    const float* Bd;
    if (routed) {
        const int e = blockIdx.z;
        offE = g_off[e]; M = g_off[e + 1] - offE;
        if (mTile * 128 >= M) return;
        actBase = T + offE;
        Bd = dwn + (size_t)e * ISZ * H + nTile * 128;
    } else {
        offE = 0; M = T; actBase = 0;
        Bd = sdwn + nTile * 128;
    }
    const int tid = threadIdx.x, lane = tid & 31, warp = tid >> 5;
    const int wm = warp & 3, wn = warp >> 2;

    const int arow = tid >> 1, akc = (tid & 1) * 8;
    const uint32_t aw = (uint32_t)(arow * 48 + (tid & 1) * 16);
    const int lr = mTile * 128 + arow;
    const float* aptr = g_act + (size_t)(actBase + min(lr, M - 1)) * ISZ + akc;

    const int bkr = tid >> 4, bn0 = (tid & 15) * 8;
    const float* bptr = Bd + (size_t)bkr * H + bn0;
    const uint32_t bw = (uint32_t)(bkr * 272 + bn0 * 2);

    const uint32_t baseA = (uint32_t)__cvta_generic_to_shared(&As[0][0][0]);
    const uint32_t baseB = (uint32_t)__cvta_generic_to_shared(&Bs[0][0][0]);
    const int SA = 128 * 48, SB = 16 * 272;

    const int tq = lane >> 3, tr = lane & 7;
    uint32_t offA[2];
#pragma unroll
    for (int mi = 0; mi < 2; mi++) {
        int row = wm * 32 + mi * 16 + (tq & 1) * 8 + tr;
        offA[mi] = (uint32_t)(row * 48 + (tq >> 1) * 16);
    }
    const int kB = (tq & 1) * 8 + tr, ngB = tq >> 1;
    uint32_t offB[4];
#pragma unroll
    for (int g = 0; g < 4; g++)
        offB[g] = (uint32_t)(kB * 272 + (wn * 64 + g * 16 + ngB * 8) * 2);

    float acc[2][8][4];
#pragma unroll
    for (int mi = 0; mi < 2; mi++)
#pragma unroll
        for (int ni = 0; ni < 8; ni++)
#pragma unroll
            for (int r = 0; r < 4; r++) acc[mi][ni][r] = 0.f;

    {
        float4 a0 = *(const float4*)aptr;
        float4 a1 = *(const float4*)(aptr + 4);
        float4 b0 = *(const float4*)bptr;
        float4 b1 = *(const float4*)(bptr + 4);
        *(uint4*)((char*)As + aw) = hpack8(a0, a1);
        *(uint4*)((char*)Bs + bw) = hpack8(b0, b1);
    }
    __syncthreads();

    const int KT = ISZ / 16;
    for (int kt = 0; kt < KT; ++kt) {
        const int s = kt & 1;
        float4 a0, a1, b0, b1;
        if (kt + 1 < KT) {
            const float* ap = aptr + (kt + 1) * 16;
            a0 = *(const float4*)ap;
            a1 = *(const float4*)(ap + 4);
            const float* bp = bptr + (size_t)(kt + 1) * 16 * H;
            b0 = *(const float4*)bp;
            b1 = *(const float4*)(bp + 4);
        }

        const uint32_t aS = baseA + s * SA;
        const uint32_t bS = baseB + s * SB;
        uint32_t af[2][4];
        ldsm_x4(af[0], aS + offA[0]);
        ldsm_x4(af[1], aS + offA[1]);
#pragma unroll
        for (int g = 0; g < 4; ++g) {
            uint32_t b4[4];
            ldsm_x4t(b4, bS + offB[g]);
#pragma unroll
            for (int sub = 0; sub < 2; ++sub) {
                const int ni = 2 * g + sub;
                uint32_t bf[2] = { b4[sub * 2], b4[sub * 2 + 1] };
#pragma unroll
                for (int mi = 0; mi < 2; ++mi)
                    MMA_F16(acc[mi][ni], af[mi], bf);
            }
        }

        if (kt + 1 < KT) {
            const int s2 = s ^ 1;
            *(uint4*)((char*)As + s2 * SA + aw) = hpack8(a0, a1);
            *(uint4*)((char*)Bs + s2 * SB + bw) = hpack8(b0, b1);
        }
        __syncthreads();
    }

#pragma unroll
    for (int mi = 0; mi < 2; ++mi) {
        const int r0 = mTile * 128 + wm * 32 + mi * 16 + (lane >> 2);
        const int r1 = r0 + 8;
        const bool v0 = r0 < M, v1 = r1 < M;
        int t0 = 0, t1 = 0;
        if (routed) {
            if (v0) t0 = g_perm[offE + r0];
            if (v1) t1 = g_perm[offE + r1];
        } else { t0 = r0; t1 = r1; }
#pragma unroll
        for (int ni = 0; ni < 8; ++ni) {
            const int col = nTile * 128 + wn * 64 + ni * 8 + (lane & 3) * 2;
            if (v0) {
                float2* p = (float2*)&out[(size_t)t0 * H + col];
                if (routed) {
                    float2 v = *p;
                    v.x += acc[mi][ni][0]; v.y += acc[mi][ni][1];
                    *p = v;
                } else {
                    *p = make_float2(acc[mi][ni][0], acc[mi][ni][1]);
                }
            }
            if (v1) {
                float2* p = (float2*)&out[(size_t)t1 * H + col];
                if (routed) {
                    float2 v = *p;
                    v.x += acc[mi][ni][2]; v.y += acc[mi][ni][3];
                    *p = v;
                } else {
                    *p = make_float2(acc[mi][ni][2], acc[mi][ni][3]);
                }
            }
        }
    }
}

// ---------------- launch ------------------------------------------------------
extern "C" void kernel_launch(void* const* d_in, const int* in_sizes, int n_in,
                              void* d_out, int out_size) {
    const float* x   = (const float*)d_in[0];
    const float* rw  = (const float*)d_in[1];
    const float* gup = (const float*)d_in[2];
    const float* dwn = (const float*)d_in[3];
    const float* sg  = (const float*)d_in[4];
    const float* su  = (const float*)d_in[5];
    const float* sd  = (const float*)d_in[6];
    float* out = (float*)d_out;

    router_kernel<<<T, 256>>>(x, rw);
    bucket_kernel<<<1, 256>>>();
    gemm1_kernel<<<dim3(16, ISZ / 64, NE + 1), 256>>>(x, gup, sg, su);
    gemm2_kernel<<<dim3(16, H / 128, 1), 256>>>(dwn, sd, out, 0);   // shared: writes out
    gemm2_kernel<<<dim3(16, H / 128, NE), 256>>>(dwn, sd, out, 1);  // routed: adds
}

// round 12
// speedup vs baseline: 2.5491x; 2.0849x over previous
#include <cuda_runtime.h>
#include <cuda_fp16.h>
#include <cstdint>

#define H   2048
#define ISZ 4096
#define NE  8
#define T   2048

// ---------------- fp16 operand scratch ----------------------------------------
__device__ __half g_wg[8UL * 2048 * 8192];    // gup fp16 (layout preserved [k][n])
__device__ __half g_wd[8UL * 4096 * 2048];    // down fp16
__device__ __half g_sg16[2048UL * 4096];
__device__ __half g_su16[2048UL * 4096];
__device__ __half g_sd16[4096UL * 2048];
__device__ __half g_x16[2048UL * 2048];
__device__ __half g_act16[4096UL * 4096];     // rows 0..2047 shared, 2048..4095 routed
__device__ float g_scale[T];
__device__ float g_scale_perm[T];
__device__ int   g_eid[T];
__device__ int   g_perm[T];
__device__ int   g_off[NE + 1];

#define MMA_F16(d, a, b)                                                       \
    asm volatile("mma.sync.aligned.m16n8k16.row.col.f32.f16.f16.f32 "          \
                 "{%0,%1,%2,%3},{%4,%5,%6,%7},{%8,%9},{%0,%1,%2,%3};"          \
                 : "+f"(d[0]), "+f"(d[1]), "+f"(d[2]), "+f"(d[3])              \
                 : "r"(a[0]), "r"(a[1]), "r"(a[2]), "r"(a[3]),                 \
                   "r"(b[0]), "r"(b[1]))

__device__ __forceinline__ void ldsm_x4(uint32_t* r, uint32_t addr) {
    asm volatile("ldmatrix.sync.aligned.m8n8.x4.shared.b16 {%0,%1,%2,%3}, [%4];"
                 : "=r"(r[0]), "=r"(r[1]), "=r"(r[2]), "=r"(r[3]) : "r"(addr));
}
__device__ __forceinline__ void ldsm_x4t(uint32_t* r, uint32_t addr) {
    asm volatile("ldmatrix.sync.aligned.m8n8.x4.trans.shared.b16 {%0,%1,%2,%3}, [%4];"
                 : "=r"(r[0]), "=r"(r[1]), "=r"(r[2]), "=r"(r[3]) : "r"(addr));
}
__device__ __forceinline__ void cp16(uint32_t s, const void* g) {
    asm volatile("cp.async.cg.shared.global [%0], [%1], 16;\n" :: "r"(s), "l"(g));
}
__device__ __forceinline__ void cp_commit() { asm volatile("cp.async.commit_group;\n"); }
__device__ __forceinline__ void cp_wait0()  { asm volatile("cp.async.wait_group 0;\n"); }
__device__ __forceinline__ void cp_wait1()  { asm volatile("cp.async.wait_group 1;\n"); }

__device__ __forceinline__ uint4 hpack8(const float4& v0, const float4& v1) {
    __half2 h0 = __floats2half2_rn(v0.x, v0.y);
    __half2 h1 = __floats2half2_rn(v0.z, v0.w);
    __half2 h2 = __floats2half2_rn(v1.x, v1.y);
    __half2 h3 = __floats2half2_rn(v1.z, v1.w);
    return make_uint4(*(uint32_t*)&h0, *(uint32_t*)&h1, *(uint32_t*)&h2, *(uint32_t*)&h3);
}

// ---------------- fp32 -> fp16 convert (layout preserved) ---------------------
__global__ void hconv_kernel(const float4* __restrict__ src, uint4* __restrict__ dst, long n16) {
    const long stride = (long)gridDim.x * blockDim.x;
    for (long i = (long)blockIdx.x * blockDim.x + threadIdx.x; i < n16; i += stride)
        dst[i] = hpack8(src[2 * i], src[2 * i + 1]);
}

__global__ void zero_kernel(float4* __restrict__ p, int n4) {
    const int stride = gridDim.x * blockDim.x;
    for (int i = blockIdx.x * blockDim.x + threadIdx.x; i < n4; i += stride)
        p[i] = make_float4(0.f, 0.f, 0.f, 0.f);
}

// ---------------- router ------------------------------------------------------
__global__ void router_kernel(const float* __restrict__ x, const float* __restrict__ rw) {
    const int t = blockIdx.x;
    const int tid = threadIdx.x;
    float acc[NE];
#pragma unroll
    for (int e = 0; e < NE; e++) acc[e] = 0.f;
    const float* xr = x + (size_t)t * H;
    for (int h = tid; h < H; h += 256) {
        float xv = xr[h];
#pragma unroll
        for (int e = 0; e < NE; e++) acc[e] += xv * rw[e * H + h];
    }
#pragma unroll
    for (int e = 0; e < NE; e++)
#pragma unroll
        for (int o = 16; o > 0; o >>= 1) acc[e] += __shfl_xor_sync(0xffffffffu, acc[e], o);
    __shared__ float red[NE][8];
    if ((tid & 31) == 0) {
#pragma unroll
        for (int e = 0; e < NE; e++) red[e][tid >> 5] = acc[e];
    }
    __syncthreads();
    if (tid == 0) {
        float best = -1e30f; int be = 0;
#pragma unroll
        for (int e = 0; e < NE; e++) {
            float v = 0.f;
#pragma unroll
            for (int w = 0; w < 8; w++) v += red[e][w];
            if (v > best) { best = v; be = e; }
        }
        g_scale[t] = 1.f / (1.f + expf(-best));
        g_eid[t] = be;
    }
}

// ---------------- bucket ------------------------------------------------------
__global__ void bucket_kernel() {
    __shared__ int cnt[NE], cur[NE];
    const int tid = threadIdx.x;
    if (tid < NE) cnt[tid] = 0;
    __syncthreads();
    for (int t = tid; t < T; t += 256) atomicAdd(&cnt[g_eid[t]], 1);
    __syncthreads();
    if (tid == 0) {
        int a = 0;
        for (int e = 0; e < NE; e++) { g_off[e] = a; cur[e] = a; a += cnt[e]; }
        g_off[NE] = a;
    }
    __syncthreads();
    for (int t = tid; t < T; t += 256) {
        int e = g_eid[t];
        int p = atomicAdd(&cur[e], 1);
        g_perm[p] = t;
        g_scale_perm[p] = g_scale[t];
    }
}

// SMEM: 3 stages x (A 128rows x 80B + B 32k x 272B) = 3 x 18944 = 56832
#define AST   10240
#define BST   8704
#define STG   18944
#define NS    3
#define SMEM_SZ (NS * STG)

// ---------------- GEMM1: x16[M,2048] x (gate|up)[2048, 64+64] + SwiGLU --------
// CTA 128m x (64g+64u), warp 32m x (32g+32u). BK=32, 3-stage cp.async, fp16.
__global__ __launch_bounds__(256) void gemm1_kernel() {
    extern __shared__ __align__(16) char smem[];
    const uint32_t sb = (uint32_t)__cvta_generic_to_shared(smem);

    const int mTile = blockIdx.x, nTile = blockIdx.y, e = blockIdx.z;
    int M, offE, actBase;
    size_t ldb;
    const __half *pg, *pu;
    if (e < NE) {
        offE = g_off[e]; M = g_off[e + 1] - offE;
        if (mTile * 128 >= M) return;
        pg = g_wg + (size_t)e * H * (2 * ISZ) + nTile * 64;
        pu = pg + ISZ; ldb = 2 * ISZ; actBase = T + offE;
    } else {
        offE = 0; M = T;
        pg = g_sg16 + nTile * 64; pu = g_su16 + nTile * 64; ldb = ISZ; actBase = 0;
    }
    const int tid = threadIdx.x, lane = tid & 31, warp = tid >> 5;
    const int wm = warp & 3, wn = warp >> 2;

    // A loader: arow = tid>>2 (0..63) -> rows arow, arow+64; chunk aq = tid&3
    const int arow = tid >> 2, aq = tid & 3;
    const int lr0 = mTile * 128 + arow, lr1 = lr0 + 64;
    int ri0, ri1;
    if (e < NE) {
        ri0 = g_perm[offE + min(lr0, M - 1)];
        ri1 = g_perm[offE + min(lr1, M - 1)];
    } else { ri0 = lr0; ri1 = lr1; }
    const __half* aptr0 = g_x16 + (size_t)ri0 * H + aq * 8;
    const __half* aptr1 = g_x16 + (size_t)ri1 * H + aq * 8;
    const uint32_t awA = arow * 80 + aq * 16;
    const uint32_t awB = (arow + 64) * 80 + aq * 16;

    // B loader: bkr = tid>>3 (0..31), bc = tid&7. gate at bytes 0..127, up 128..255.
    const int bkr = tid >> 3, bc = tid & 7;
    const __half* pgt = pg + (size_t)bkr * ldb + bc * 8;
    const __half* put = pu + (size_t)bkr * ldb + bc * 8;
    const uint32_t bwG = bkr * 272 + bc * 16;
    const uint32_t bwU = bkr * 272 + 128 + bc * 16;

    // fragment offsets
    const int tq = lane >> 3, tr = lane & 7;
    uint32_t offA[2];
#pragma unroll
    for (int mi = 0; mi < 2; mi++) {
        int row = wm * 32 + mi * 16 + (tq & 1) * 8 + tr;
        offA[mi] = (uint32_t)(row * 80 + (tq >> 1) * 16);
    }
    const int kB = (tq & 1) * 8 + tr, ngB = tq >> 1;
    uint32_t offB[2][2];
#pragma unroll
    for (int hh = 0; hh < 2; hh++)
#pragma unroll
        for (int g = 0; g < 2; g++)
            offB[hh][g] = (uint32_t)(kB * 272 + hh * 128 + (wn * 32 + g * 16 + ngB * 8) * 2);

    float acc[2][2][4][4];
#pragma unroll
    for (int h = 0; h < 2; h++)
#pragma unroll
        for (int mi = 0; mi < 2; mi++)
#pragma unroll
            for (int ni = 0; ni < 4; ni++)
#pragma unroll
                for (int r = 0; r < 4; r++) acc[h][mi][ni][r] = 0.f;

#define G1_FILL(s, k0)                                                          \
    {                                                                           \
        const uint32_t stg = sb + (s) * STG;                                    \
        cp16(stg + awA, aptr0 + (k0));                                          \
        cp16(stg + awB, aptr1 + (k0));                                          \
        const size_t ko = (size_t)(k0) * ldb;                                   \
        cp16(stg + AST + bwG, pgt + ko);                                        \
        cp16(stg + AST + bwU, put + ko);                                        \
    }

    const int KT = H / 32;
    G1_FILL(0, 0)  cp_commit();
    G1_FILL(1, 32) cp_commit();

    for (int c = 0; c < KT; ++c) {
        const int s = c % NS;
        if (c + 2 < KT) cp_wait1(); else cp_wait0();
        __syncthreads();
        if (c + 2 < KT) { G1_FILL((c + 2) % NS, (c + 2) * 32) }
        cp_commit();

        const uint32_t aS = sb + s * STG;
        const uint32_t bS = aS + AST;
#pragma unroll
        for (int ks = 0; ks < 2; ++ks) {
            uint32_t af[2][4];
            ldsm_x4(af[0], aS + offA[0] + ks * 32);
            ldsm_x4(af[1], aS + offA[1] + ks * 32);
#pragma unroll
            for (int hh = 0; hh < 2; ++hh) {
#pragma unroll
                for (int g = 0; g < 2; ++g) {
                    uint32_t b4[4];
                    ldsm_x4t(b4, bS + offB[hh][g] + ks * 16 * 272);
#pragma unroll
                    for (int sub = 0; sub < 2; ++sub) {
                        const int ni = 2 * g + sub;
                        uint32_t bf[2] = { b4[sub * 2], b4[sub * 2 + 1] };
#pragma unroll
                        for (int mi = 0; mi < 2; ++mi)
                            MMA_F16(acc[hh][mi][ni], af[mi], bf);
                    }
                }
            }
        }
    }

    // epilogue: act = (s*up) * silu(s*gate) -> fp16
#pragma unroll
    for (int mi = 0; mi < 2; ++mi) {
        const int r0 = mTile * 128 + wm * 32 + mi * 16 + (lane >> 2);
        const int r1 = r0 + 8;
        const bool v0 = r0 < M, v1 = r1 < M;
        float s0 = 1.f, s1 = 1.f;
        if (e < NE) {
            s0 = v0 ? g_scale_perm[offE + r0] : 0.f;
            s1 = v1 ? g_scale_perm[offE + r1] : 0.f;
        }
#pragma unroll
        for (int ni = 0; ni < 4; ++ni) {
            const int col = nTile * 64 + wn * 32 + ni * 8 + (lane & 3) * 2;
            if (v0) {
                float gA = s0 * acc[0][mi][ni][0], gB = s0 * acc[0][mi][ni][1];
                float uA = s0 * acc[1][mi][ni][0], uB = s0 * acc[1][mi][ni][1];
                __half2 h = __floats2half2_rn(uA * (gA / (1.f + expf(-gA))),
                                              uB * (gB / (1.f + expf(-gB))));
                *(uint32_t*)&g_act16[(size_t)(actBase + r0) * ISZ + col] = *(uint32_t*)&h;
            }
            if (v1) {
                float gA = s1 * acc[0][mi][ni][2], gB = s1 * acc[0][mi][ni][3];
                float uA = s1 * acc[1][mi][ni][2], uB = s1 * acc[1][mi][ni][3];
                __half2 h = __floats2half2_rn(uA * (gA / (1.f + expf(-gA))),
                                              uB * (gB / (1.f + expf(-gB))));
                *(uint32_t*)&g_act16[(size_t)(actBase + r1) * ISZ + col] = *(uint32_t*)&h;
            }
        }
    }
}

// ---------------- GEMM2 (merged): act16[M,4096] x down16[4096,2048] -----------
// z = 0..7 routed experts, z = 8 shared. atomicAdd epilogue onto zeroed out.
__global__ __launch_bounds__(256) void gemm2_kernel(float* __restrict__ out) {
    extern __shared__ __align__(16) char smem[];
    const uint32_t sb = (uint32_t)__cvta_generic_to_shared(smem);

    const int mTile = blockIdx.x, nTile = blockIdx.y, z = blockIdx.z;
    const int routed = (z < NE);
    int M, offE, actBase;
    const __half* Bd;
    if (routed) {
        offE = g_off[z]; M = g_off[z + 1] - offE;
        if (mTile * 128 >= M) return;
        actBase = T + offE;
        Bd = g_wd + (size_t)z * ISZ * H + nTile * 128;
    } else {
        offE = 0; M = T; actBase = 0;
        Bd = g_sd16 + nTile * 128;
    }
    const int tid = threadIdx.x, lane = tid & 31, warp = tid >> 5;
    const int wm = warp & 3, wn = warp >> 2;

    const int arow = tid >> 2, aq = tid & 3;
    const int lr0 = mTile * 128 + arow, lr1 = lr0 + 64;
    const __half* aptr0 = g_act16 + (size_t)(actBase + min(lr0, M - 1)) * ISZ + aq * 8;
    const __half* aptr1 = g_act16 + (size_t)(actBase + min(lr1, M - 1)) * ISZ + aq * 8;
    const uint32_t awA = arow * 80 + aq * 16;
    const uint32_t awB = (arow + 64) * 80 + aq * 16;

    const int bkr = tid >> 3, bc = tid & 7;
    const __half* pbt = Bd + (size_t)bkr * H + bc * 16;
    const uint32_t bw0 = bkr * 272 + bc * 32;

    const int tq = lane >> 3, tr = lane & 7;
    uint32_t offA[2];
#pragma unroll
    for (int mi = 0; mi < 2; mi++) {
        int row = wm * 32 + mi * 16 + (tq & 1) * 8 + tr;
        offA[mi] = (uint32_t)(row * 80 + (tq >> 1) * 16);
    }
    const int kB = (tq & 1) * 8 + tr, ngB = tq >> 1;
    uint32_t offB[4];
#pragma unroll
    for (int g = 0; g < 4; g++)
        offB[g] = (uint32_t)(kB * 272 + (wn * 64 + g * 16 + ngB * 8) * 2);

    float acc[2][8][4];
#pragma unroll
    for (int mi = 0; mi < 2; mi++)
#pragma unroll
        for (int ni = 0; ni < 8; ni++)
#pragma unroll
            for (int r = 0; r < 4; r++) acc[mi][ni][r] = 0.f;

#define G2_FILL(s, k0)                                                          \
    {                                                                           \
        const uint32_t stg = sb + (s) * STG;                                    \
        cp16(stg + awA, aptr0 + (k0));                                          \
        cp16(stg + awB, aptr1 + (k0));                                          \
        const size_t ko = (size_t)(k0) * H;                                     \
        cp16(stg + AST + bw0, pbt + ko);                                        \
        cp16(stg + AST + bw0 + 16, pbt + ko + 8);                               \
    }

    const int KT = ISZ / 32;
    G2_FILL(0, 0)  cp_commit();
    G2_FILL(1, 32) cp_commit();

    for (int c = 0; c < KT; ++c) {
        const int s = c % NS;
        if (c + 2 < KT) cp_wait1(); else cp_wait0();
        __syncthreads();
        if (c + 2 < KT) { G2_FILL((c + 2) % NS, (c + 2) * 32) }
        cp_commit();

        const uint32_t aS = sb + s * STG;
        const uint32_t bS = aS + AST;
#pragma unroll
        for (int ks = 0; ks < 2; ++ks) {
            uint32_t af[2][4];
            ldsm_x4(af[0], aS + offA[0] + ks * 32);
            ldsm_x4(af[1], aS + offA[1] + ks * 32);
#pragma unroll
            for (int g = 0; g < 4; ++g) {
                uint32_t b4[4];
                ldsm_x4t(b4, bS + offB[g] + ks * 16 * 272);
#pragma unroll
                for (int sub = 0; sub < 2; ++sub) {
                    const int ni = 2 * g + sub;
                    uint32_t bf[2] = { b4[sub * 2], b4[sub * 2 + 1] };
#pragma unroll
                    for (int mi = 0; mi < 2; ++mi)
                        MMA_F16(acc[mi][ni], af[mi], bf);
                }
            }
        }
    }

#pragma unroll
    for (int mi = 0; mi < 2; ++mi) {
        const int r0 = mTile * 128 + wm * 32 + mi * 16 + (lane >> 2);
        const int r1 = r0 + 8;
        const bool v0 = r0 < M, v1 = r1 < M;
        int t0 = 0, t1 = 0;
        if (routed) {
            if (v0) t0 = g_perm[offE + r0];
            if (v1) t1 = g_perm[offE + r1];
        } else { t0 = r0; t1 = r1; }
#pragma unroll
        for (int ni = 0; ni < 8; ++ni) {
            const int col = nTile * 128 + wn * 64 + ni * 8 + (lane & 3) * 2;
            if (v0) {
                float* p = &out[(size_t)t0 * H + col];
                atomicAdd(p, acc[mi][ni][0]);
                atomicAdd(p + 1, acc[mi][ni][1]);
            }
            if (v1) {
                float* p = &out[(size_t)t1 * H + col];
                atomicAdd(p, acc[mi][ni][2]);
                atomicAdd(p + 1, acc[mi][ni][3]);
            }
        }
    }
}

// ---------------- launch ------------------------------------------------------
extern "C" void kernel_launch(void* const* d_in, const int* in_sizes, int n_in,
                              void* d_out, int out_size) {
    const float* x   = (const float*)d_in[0];
    const float* rw  = (const float*)d_in[1];
    const float* gup = (const float*)d_in[2];
    const float* dwn = (const float*)d_in[3];
    const float* sg  = (const float*)d_in[4];
    const float* su  = (const float*)d_in[5];
    const float* sd  = (const float*)d_in[6];
    float* out = (float*)d_out;

    cudaFuncSetAttribute(gemm1_kernel, cudaFuncAttributeMaxDynamicSharedMemorySize, SMEM_SZ);
    cudaFuncSetAttribute(gemm2_kernel, cudaFuncAttributeMaxDynamicSharedMemorySize, SMEM_SZ);

    void *wg, *wd, *sg16, *su16, *sd16, *x16;
    cudaGetSymbolAddress(&wg, g_wg);     cudaGetSymbolAddress(&wd, g_wd);
    cudaGetSymbolAddress(&sg16, g_sg16); cudaGetSymbolAddress(&su16, g_su16);
    cudaGetSymbolAddress(&sd16, g_sd16); cudaGetSymbolAddress(&x16, g_x16);

    router_kernel<<<T, 256>>>(x, rw);
    bucket_kernel<<<1, 256>>>();

    hconv_kernel<<<8192, 256>>>((const float4*)gup, (uint4*)wg,   8L * 2048 * 8192 / 8);
    hconv_kernel<<<8192, 256>>>((const float4*)dwn, (uint4*)wd,   8L * 4096 * 2048 / 8);
    hconv_kernel<<<2048, 256>>>((const float4*)sg,  (uint4*)sg16, 2048L * 4096 / 8);
    hconv_kernel<<<2048, 256>>>((const float4*)su,  (uint4*)su16, 2048L * 4096 / 8);
    hconv_kernel<<<2048, 256>>>((const float4*)sd,  (uint4*)sd16, 4096L * 2048 / 8);
    hconv_kernel<<<1024, 256>>>((const float4*)x,   (uint4*)x16,  2048L * 2048 / 8);
    zero_kernel<<<1024, 256>>>((float4*)out, T * H / 4);

    gemm1_kernel<<<dim3(16, ISZ / 64, NE + 1), 256, SMEM_SZ>>>();
    gemm2_kernel<<<dim3(16, H / 128, NE + 1), 256, SMEM_SZ>>>(out);
}

// round 15
// speedup vs baseline: 2.5673x; 1.0071x over previous
#include <cuda_runtime.h>
#include <cuda_fp16.h>
#include <cstdint>

#define H   2048
#define ISZ 4096
#define NE  8
#define T   2048

// ---------------- fp16 operand scratch ----------------------------------------
__device__ __half g_wg[8UL * 2048 * 8192];    // gup fp16 (layout preserved [k][n])
__device__ __half g_wd[8UL * 4096 * 2048];    // down fp16
__device__ __half g_sg16[2048UL * 4096];
__device__ __half g_su16[2048UL * 4096];
__device__ __half g_sd16[4096UL * 2048];
__device__ __half g_x16[2048UL * 2048];
__device__ __half g_act16[4096UL * 4096];     // rows 0..2047 shared, 2048..4095 routed
__device__ float g_scale[T];
__device__ float g_scale_perm[T];
__device__ int   g_eid[T];
__device__ int   g_perm[T];
__device__ int   g_off[NE + 1];

#define MMA_F16(d, a, b)                                                       \
    asm volatile("mma.sync.aligned.m16n8k16.row.col.f32.f16.f16.f32 "          \
                 "{%0,%1,%2,%3},{%4,%5,%6,%7},{%8,%9},{%0,%1,%2,%3};"          \
                 : "+f"(d[0]), "+f"(d[1]), "+f"(d[2]), "+f"(d[3])              \
                 : "r"(a[0]), "r"(a[1]), "r"(a[2]), "r"(a[3]),                 \
                   "r"(b[0]), "r"(b[1]))

__device__ __forceinline__ void ldsm_x4(uint32_t* r, uint32_t addr) {
    asm volatile("ldmatrix.sync.aligned.m8n8.x4.shared.b16 {%0,%1,%2,%3}, [%4];"
                 : "=r"(r[0]), "=r"(r[1]), "=r"(r[2]), "=r"(r[3]) : "r"(addr));
}
__device__ __forceinline__ void ldsm_x4t(uint32_t* r, uint32_t addr) {
    asm volatile("ldmatrix.sync.aligned.m8n8.x4.trans.shared.b16 {%0,%1,%2,%3}, [%4];"
                 : "=r"(r[0]), "=r"(r[1]), "=r"(r[2]), "=r"(r[3]) : "r"(addr));
}
__device__ __forceinline__ void cp16(uint32_t s, const void* g) {
    asm volatile("cp.async.cg.shared.global [%0], [%1], 16;\n" :: "r"(s), "l"(g));
}
__device__ __forceinline__ void cp_commit() { asm volatile("cp.async.commit_group;\n"); }
__device__ __forceinline__ void cp_wait0()  { asm volatile("cp.async.wait_group 0;\n"); }
__device__ __forceinline__ void cp_wait2()  { asm volatile("cp.async.wait_group 2;\n"); }

__device__ __forceinline__ uint4 hpack8(const float4& v0, const float4& v1) {
    __half2 h0 = __floats2half2_rn(v0.x, v0.y);
    __half2 h1 = __floats2half2_rn(v0.z, v0.w);
    __half2 h2 = __floats2half2_rn(v1.x, v1.y);
    __half2 h3 = __floats2half2_rn(v1.z, v1.w);
    return make_uint4(*(uint32_t*)&h0, *(uint32_t*)&h1, *(uint32_t*)&h2, *(uint32_t*)&h3);
}

// ---------------- fp32 -> fp16 convert (layout preserved) ---------------------
__global__ void hconv_kernel(const float4* __restrict__ src, uint4* __restrict__ dst, long n16) {
    const long stride = (long)gridDim.x * blockDim.x;
    for (long i = (long)blockIdx.x * blockDim.x + threadIdx.x; i < n16; i += stride)
        dst[i] = hpack8(src[2 * i], src[2 * i + 1]);
}

__global__ void zero_kernel(float4* __restrict__ p, int n4) {
    const int stride = gridDim.x * blockDim.x;
    for (int i = blockIdx.x * blockDim.x + threadIdx.x; i < n4; i += stride)
        p[i] = make_float4(0.f, 0.f, 0.f, 0.f);
}

// ---------------- router ------------------------------------------------------
__global__ void router_kernel(const float* __restrict__ x, const float* __restrict__ rw) {
    const int t = blockIdx.x;
    const int tid = threadIdx.x;
    float acc[NE];
#pragma unroll
    for (int e = 0; e < NE; e++) acc[e] = 0.f;
    const float* xr = x + (size_t)t * H;
    for (int h = tid; h < H; h += 256) {
        float xv = xr[h];
#pragma unroll
        for (int e = 0; e < NE; e++) acc[e] += xv * rw[e * H + h];
    }
#pragma unroll
    for (int e = 0; e < NE; e++)
#pragma unroll
        for (int o = 16; o > 0; o >>= 1) acc[e] += __shfl_xor_sync(0xffffffffu, acc[e], o);
    __shared__ float red[NE][8];
    if ((tid & 31) == 0) {
#pragma unroll
        for (int e = 0; e < NE; e++) red[e][tid >> 5] = acc[e];
    }
    __syncthreads();
    if (tid == 0) {
        float best = -1e30f; int be = 0;
#pragma unroll
        for (int e = 0; e < NE; e++) {
            float v = 0.f;
#pragma unroll
            for (int w = 0; w < 8; w++) v += red[e][w];
            if (v > best) { best = v; be = e; }
        }
        g_scale[t] = 1.f / (1.f + expf(-best));
        g_eid[t] = be;
    }
}

// ---------------- bucket ------------------------------------------------------
__global__ void bucket_kernel() {
    __shared__ int cnt[NE], cur[NE];
    const int tid = threadIdx.x;
    if (tid < NE) cnt[tid] = 0;
    __syncthreads();
    for (int t = tid; t < T; t += 256) atomicAdd(&cnt[g_eid[t]], 1);
    __syncthreads();
    if (tid == 0) {
        int a = 0;
        for (int e = 0; e < NE; e++) { g_off[e] = a; cur[e] = a; a += cnt[e]; }
        g_off[NE] = a;
    }
    __syncthreads();
    for (int t = tid; t < T; t += 256) {
        int e = g_eid[t];
        int p = atomicAdd(&cur[e], 1);
        g_perm[p] = t;
        g_scale_perm[p] = g_scale[t];
    }
}

// SMEM: 4 stages x (A 128rows x 80B + B 32k x 272B) = 4 x 18944 = 75776
#define AST   10240
#define STG   18944
#define NS    4
#define SMEM_SZ (NS * STG)

// ---------------- GEMM1: x16[M,2048] x (gate|up)[2048, 64+64] + SwiGLU --------
// CTA 128m x (64g+64u), warp 32m x (32g+32u). BK=32, 4-stage cp.async, fp16.
__global__ __launch_bounds__(256) void gemm1_kernel() {
    extern __shared__ __align__(16) char smem[];
    const uint32_t sb = (uint32_t)__cvta_generic_to_shared(smem);

    const int mTile = blockIdx.x, nTile = blockIdx.y, e = blockIdx.z;
    int M, offE, actBase;
    size_t ldb;
    const __half *pg, *pu;
    if (e < NE) {
        offE = g_off[e]; M = g_off[e + 1] - offE;
        if (mTile * 128 >= M) return;
        pg = g_wg + (size_t)e * H * (2 * ISZ) + nTile * 64;
        pu = pg + ISZ; ldb = 2 * ISZ; actBase = T + offE;
    } else {
        offE = 0; M = T;
        pg = g_sg16 + nTile * 64; pu = g_su16 + nTile * 64; ldb = ISZ; actBase = 0;
    }
    const int tid = threadIdx.x, lane = tid & 31, warp = tid >> 5;
    const int wm = warp & 3, wn = warp >> 2;

    // A loader: arow = tid>>2 (0..63) -> rows arow, arow+64; chunk aq = tid&3
    const int arow = tid >> 2, aq = tid & 3;
    const int lr0 = mTile * 128 + arow, lr1 = lr0 + 64;
    int ri0, ri1;
    if (e < NE) {
        ri0 = g_perm[offE + min(lr0, M - 1)];
        ri1 = g_perm[offE + min(lr1, M - 1)];
    } else { ri0 = lr0; ri1 = lr1; }
    const __half* aptr0 = g_x16 + (size_t)ri0 * H + aq * 8;
    const __half* aptr1 = g_x16 + (size_t)ri1 * H + aq * 8;
    const uint32_t awA = arow * 80 + aq * 16;
    const uint32_t awB = (arow + 64) * 80 + aq * 16;

    // B loader: bkr = tid>>3 (0..31), bc = tid&7. gate at bytes 0..127, up 128..255.
    const int bkr = tid >> 3, bc = tid & 7;
    const __half* pgt = pg + (size_t)bkr * ldb + bc * 8;
    const __half* put = pu + (size_t)bkr * ldb + bc * 8;
    const uint32_t bwG = bkr * 272 + bc * 16;
    const uint32_t bwU = bkr * 272 + 128 + bc * 16;

    // fragment offsets
    const int tq = lane >> 3, tr = lane & 7;
    uint32_t offA[2];
#pragma unroll
    for (int mi = 0; mi < 2; mi++) {
        int row = wm * 32 + mi * 16 + (tq & 1) * 8 + tr;
        offA[mi] = (uint32_t)(row * 80 + (tq >> 1) * 16);
    }
    const int kB = (tq & 1) * 8 + tr, ngB = tq >> 1;
    uint32_t offB[2][2];
#pragma unroll
    for (int hh = 0; hh < 2; hh++)
#pragma unroll
        for (int g = 0; g < 2; g++)
            offB[hh][g] = (uint32_t)(kB * 272 + hh * 128 + (wn * 32 + g * 16 + ngB * 8) * 2);

    float acc[2][2][4][4];
#pragma unroll
    for (int h = 0; h < 2; h++)
#pragma unroll
        for (int mi = 0; mi < 2; mi++)
#pragma unroll
            for (int ni = 0; ni < 4; ni++)
#pragma unroll
                for (int r = 0; r < 4; r++) acc[h][mi][ni][r] = 0.f;

#define G1_FILL(s, k0)                                                          \
    {                                                                           \
        const uint32_t stg = sb + (s) * STG;                                    \
        cp16(stg + awA, aptr0 + (k0));                                          \
        cp16(stg + awB, aptr1 + (k0));                                          \
        const size_t ko = (size_t)(k0) * ldb;                                   \
        cp16(stg + AST + bwG, pgt + ko);                                        \
        cp16(stg + AST + bwU, put + ko);                                        \
    }

    const int KT = H / 32;
    G1_FILL(0, 0)  cp_commit();
    G1_FILL(1, 32) cp_commit();
    G1_FILL(2, 64) cp_commit();

    for (int c = 0; c < KT; ++c) {
        const int s = c & 3;
        cp_wait2();
        __syncthreads();
        if (c + 3 < KT) { G1_FILL((c + 3) & 3, (c + 3) * 32) }
        cp_commit();

        const uint32_t aS = sb + s * STG;
        const uint32_t bS = aS + AST;
#pragma unroll
        for (int ks = 0; ks < 2; ++ks) {
            uint32_t af[2][4];
            ldsm_x4(af[0], aS + offA[0] + ks * 32);
            ldsm_x4(af[1], aS + offA[1] + ks * 32);
#pragma unroll
            for (int hh = 0; hh < 2; ++hh) {
#pragma unroll
                for (int g = 0; g < 2; ++g) {
                    uint32_t b4[4];
                    ldsm_x4t(b4, bS + offB[hh][g] + ks * 16 * 272);
#pragma unroll
                    for (int sub = 0; sub < 2; ++sub) {
                        const int ni = 2 * g + sub;
                        uint32_t bf[2] = { b4[sub * 2], b4[sub * 2 + 1] };
#pragma unroll
                        for (int mi = 0; mi < 2; ++mi)
                            MMA_F16(acc[hh][mi][ni], af[mi], bf);
                    }
                }
            }
        }
    }

    // epilogue: act = (s*up) * silu(s*gate) -> fp16
#pragma unroll
    for (int mi = 0; mi < 2; ++mi) {
        const int r0 = mTile * 128 + wm * 32 + mi * 16 + (lane >> 2);
        const int r1 = r0 + 8;
        const bool v0 = r0 < M, v1 = r1 < M;
        float s0 = 1.f, s1 = 1.f;
        if (e < NE) {
            s0 = v0 ? g_scale_perm[offE + r0] : 0.f;
            s1 = v1 ? g_scale_perm[offE + r1] : 0.f;
        }
#pragma unroll
        for (int ni = 0; ni < 4; ++ni) {
            const int col = nTile * 64 + wn * 32 + ni * 8 + (lane & 3) * 2;
            if (v0) {
                float gA = s0 * acc[0][mi][ni][0], gB = s0 * acc[0][mi][ni][1];
                float uA = s0 * acc[1][mi][ni][0], uB = s0 * acc[1][mi][ni][1];
                __half2 h = __floats2half2_rn(uA * (gA / (1.f + expf(-gA))),
                                              uB * (gB / (1.f + expf(-gB))));
                *(uint32_t*)&g_act16[(size_t)(actBase + r0) * ISZ + col] = *(uint32_t*)&h;
            }
            if (v1) {
                float gA = s1 * acc[0][mi][ni][2], gB = s1 * acc[0][mi][ni][3];
                float uA = s1 * acc[1][mi][ni][2], uB = s1 * acc[1][mi][ni][3];
                __half2 h = __floats2half2_rn(uA * (gA / (1.f + expf(-gA))),
                                              uB * (gB / (1.f + expf(-gB))));
                *(uint32_t*)&g_act16[(size_t)(actBase + r1) * ISZ + col] = *(uint32_t*)&h;
            }
        }
    }
}

// ---------------- GEMM2 (merged): act16[M,4096] x down16[4096,2048] -----------
// z = 0..7 routed experts, z = 8 shared. atomicAdd epilogue onto zeroed out.
__global__ __launch_bounds__(256) void gemm2_kernel(float* __restrict__ out) {
    extern __shared__ __align__(16) char smem[];
    const uint32_t sb = (uint32_t)__cvta_generic_to_shared(smem);

    const int mTile = blockIdx.x, nTile = blockIdx.y, z = blockIdx.z;
    const int routed = (z < NE);
    int M, offE, actBase;
    const __half* Bd;
    if (routed) {
        offE = g_off[z]; M = g_off[z + 1] - offE;
        if (mTile * 128 >= M) return;
        actBase = T + offE;
        Bd = g_wd + (size_t)z * ISZ * H + nTile * 128;
    } else {
        offE = 0; M = T; actBase = 0;
        Bd = g_sd16 + nTile * 128;
    }
    const int tid = threadIdx.x, lane = tid & 31, warp = tid >> 5;
    const int wm = warp & 3, wn = warp >> 2;

    const int arow = tid >> 2, aq = tid & 3;
    const int lr0 = mTile * 128 + arow, lr1 = lr0 + 64;
    const __half* aptr0 = g_act16 + (size_t)(actBase + min(lr0, M - 1)) * ISZ + aq * 8;
    const __half* aptr1 = g_act16 + (size_t)(actBase + min(lr1, M - 1)) * ISZ + aq * 8;
    const uint32_t awA = arow * 80 + aq * 16;
    const uint32_t awB = (arow + 64) * 80 + aq * 16;

    const int bkr = tid >> 3, bc = tid & 7;
    const __half* pbt = Bd + (size_t)bkr * H + bc * 16;
    const uint32_t bw0 = bkr * 272 + bc * 32;

    const int tq = lane >> 3, tr = lane & 7;
    uint32_t offA[2];
#pragma unroll
    for (int mi = 0; mi < 2; mi++) {
        int row = wm * 32 + mi * 16 + (tq & 1) * 8 + tr;
        offA[mi] = (uint32_t)(row * 80 + (tq >> 1) * 16);
    }
    const int kB = (tq & 1) * 8 + tr, ngB = tq >> 1;
    uint32_t offB[4];
#pragma unroll
    for (int g = 0; g < 4; g++)
        offB[g] = (uint32_t)(kB * 272 + (wn * 64 + g * 16 + ngB * 8) * 2);

    float acc[2][8][4];
#pragma unroll
    for (int mi = 0; mi < 2; mi++)
#pragma unroll
        for (int ni = 0; ni < 8; ni++)
#pragma unroll
            for (int r = 0; r < 4; r++) acc[mi][ni][r] = 0.f;

#define G2_FILL(s, k0)                                                          \
    {                                                                           \
        const uint32_t stg = sb + (s) * STG;                                    \
        cp16(stg + awA, aptr0 + (k0));                                          \
        cp16(stg + awB, aptr1 + (k0));                                          \
        const size_t ko = (size_t)(k0) * H;                                     \
        cp16(stg + AST + bw0, pbt + ko);                                        \
        cp16(stg + AST + bw0 + 16, pbt + ko + 8);                               \
    }

    const int KT = ISZ / 32;
    G2_FILL(0, 0)  cp_commit();
    G2_FILL(1, 32) cp_commit();
    G2_FILL(2, 64) cp_commit();

    for (int c = 0; c < KT; ++c) {
        const int s = c & 3;
        cp_wait2();
        __syncthreads();
        if (c + 3 < KT) { G2_FILL((c + 3) & 3, (c + 3) * 32) }
        cp_commit();

        const uint32_t aS = sb + s * STG;
        const uint32_t bS = aS + AST;
#pragma unroll
        for (int ks = 0; ks < 2; ++ks) {
            uint32_t af[2][4];
            ldsm_x4(af[0], aS + offA[0] + ks * 32);
            ldsm_x4(af[1], aS + offA[1] + ks * 32);
#pragma unroll
            for (int g = 0; g < 4; ++g) {
                uint32_t b4[4];
                ldsm_x4t(b4, bS + offB[g] + ks * 16 * 272);
#pragma unroll
                for (int sub = 0; sub < 2; ++sub) {
                    const int ni = 2 * g + sub;
                    uint32_t bf[2] = { b4[sub * 2], b4[sub * 2 + 1] };
#pragma unroll
                    for (int mi = 0; mi < 2; ++mi)
                        MMA_F16(acc[mi][ni], af[mi], bf);
                }
            }
        }
    }

#pragma unroll
    for (int mi = 0; mi < 2; ++mi) {
        const int r0 = mTile * 128 + wm * 32 + mi * 16 + (lane >> 2);
        const int r1 = r0 + 8;
        const bool v0 = r0 < M, v1 = r1 < M;
        int t0 = 0, t1 = 0;
        if (routed) {
            if (v0) t0 = g_perm[offE + r0];
            if (v1) t1 = g_perm[offE + r1];
        } else { t0 = r0; t1 = r1; }
#pragma unroll
        for (int ni = 0; ni < 8; ++ni) {
            const int col = nTile * 128 + wn * 64 + ni * 8 + (lane & 3) * 2;
            if (v0) {
                float* p = &out[(size_t)t0 * H + col];
                atomicAdd(p, acc[mi][ni][0]);
                atomicAdd(p + 1, acc[mi][ni][1]);
            }
            if (v1) {
                float* p = &out[(size_t)t1 * H + col];
                atomicAdd(p, acc[mi][ni][2]);
                atomicAdd(p + 1, acc[mi][ni][3]);
            }
        }
    }
}

// ---------------- launch ------------------------------------------------------
extern "C" void kernel_launch(void* const* d_in, const int* in_sizes, int n_in,
                              void* d_out, int out_size) {
    const float* x   = (const float*)d_in[0];
    const float* rw  = (const float*)d_in[1];
    const float* gup = (const float*)d_in[2];
    const float* dwn = (const float*)d_in[3];
    const float* sg  = (const float*)d_in[4];
    const float* su  = (const float*)d_in[5];
    const float* sd  = (const float*)d_in[6];
    float* out = (float*)d_out;

    cudaFuncSetAttribute(gemm1_kernel, cudaFuncAttributeMaxDynamicSharedMemorySize, SMEM_SZ);
    cudaFuncSetAttribute(gemm2_kernel, cudaFuncAttributeMaxDynamicSharedMemorySize, SMEM_SZ);

    void *wg, *wd, *sg16, *su16, *sd16, *x16;
    cudaGetSymbolAddress(&wg, g_wg);     cudaGetSymbolAddress(&wd, g_wd);
    cudaGetSymbolAddress(&sg16, g_sg16); cudaGetSymbolAddress(&su16, g_su16);
    cudaGetSymbolAddress(&sd16, g_sd16); cudaGetSymbolAddress(&x16, g_x16);

    // side stream: converts needed only by gemm2 (down, shared_down) overlap gemm1
    cudaStream_t s1;
    cudaStreamCreate(&s1);
    cudaEvent_t e0, e1;
    cudaEventCreateWithFlags(&e0, cudaEventDisableTiming);
    cudaEventCreateWithFlags(&e1, cudaEventDisableTiming);

    cudaEventRecord(e0, 0);
    cudaStreamWaitEvent(s1, e0, 0);
    hconv_kernel<<<8192, 256, 0, s1>>>((const float4*)dwn, (uint4*)wd, 8L * 4096 * 2048 / 8);
    hconv_kernel<<<2048, 256, 0, s1>>>((const float4*)sd,  (uint4*)sd16, 4096L * 2048 / 8);
    cudaEventRecord(e1, s1);

    router_kernel<<<T, 256>>>(x, rw);
    bucket_kernel<<<1, 256>>>();
    hconv_kernel<<<8192, 256>>>((const float4*)gup, (uint4*)wg,   8L * 2048 * 8192 / 8);
    hconv_kernel<<<2048, 256>>>((const float4*)sg,  (uint4*)sg16, 2048L * 4096 / 8);
    hconv_kernel<<<2048, 256>>>((const float4*)su,  (uint4*)su16, 2048L * 4096 / 8);
    hconv_kernel<<<1024, 256>>>((const float4*)x,   (uint4*)x16,  2048L * 2048 / 8);
    zero_kernel<<<1024, 256>>>((float4*)out, T * H / 4);

    gemm1_kernel<<<dim3(16, ISZ / 64, NE + 1), 256, SMEM_SZ>>>();

    cudaStreamWaitEvent(0, e1, 0);
    gemm2_kernel<<<dim3(16, H / 128, NE + 1), 256, SMEM_SZ>>>(out);

    cudaStreamDestroy(s1);
    cudaEventDestroy(e0);
    cudaEventDestroy(e1);
}